// round 5
// baseline (speedup 1.0000x reference)
#include <cuda_runtime.h>
#include <math.h>

#define SB 8
#define CH 32
#define KM 32
#define OC 32
#define SS 2048
#define DF (1.0f/2047.0f)

// ---- scratch (device globals: allocation-free rule) ----
__device__ __align__(16) float g_xsum[SB*SS];            // [b][s]
__device__ float g_cpart[256*CH];                        // per-block per-channel partials
__device__ __align__(16) float g_P[(size_t)SB*KM*SS];    // [b][k][t] fwd decay scan
__device__ __align__(16) float g_Q[(size_t)SB*KM*SS];    // [b][k][t] bwd decay scan
__device__ __align__(16) float g_wsum[KM*OC];            // [k][o]
__device__ float g_a[KM], g_aG[KM], g_poles[KM];
__device__ float g_D;
__device__ int g_cnt;                                    // last-block counter (self-resetting)

// replicate reference float32 coords: linspace(0,1,2048)
__device__ __forceinline__ float coordf(int i) {
    return (i == SS - 1) ? 1.0f : ((float)i) * DF;
}

// ------- Stage 0: xsum + cpart (256 blocks, 1 LDG.128/thread); last block -> poles -------
__global__ __launch_bounds__(512) void k_pre(
    const float* __restrict__ x, const float* __restrict__ wla,
    const float* __restrict__ wph, const float* __restrict__ c_star,
    const float* __restrict__ dt_star, const float* __restrict__ log_poles,
    const float* __restrict__ pole_w, const float* __restrict__ pole_b)
{
    __shared__ __align__(16) float4 sacc[32][16];
    __shared__ float sws[16][32];
    __shared__ float sxm[32][17];
    __shared__ int lastFlag;
    int bx = blockIdx.x;
    int b = bx >> 5, sc = bx & 31;          // 32 s-chunks of 64 elements
    int tid = threadIdx.x;
    int c = tid >> 4, q = tid & 15;         // channel, quad-within-chunk
    int lane = tid & 31;

    float4 v = ((const float4*)x)[(size_t)(b * CH + c) * (SS / 4) + sc * 16 + q];
    sacc[c][q] = v;
    float cp = (v.x + v.y) + (v.z + v.w);
    cp += __shfl_xor_sync(0xffffffffu, cp, 1);
    cp += __shfl_xor_sync(0xffffffffu, cp, 2);
    cp += __shfl_xor_sync(0xffffffffu, cp, 4);
    cp += __shfl_xor_sync(0xffffffffu, cp, 8);
    if ((lane & 15) == 0) g_cpart[bx * 32 + c] = cp;
    __syncthreads();
    #pragma unroll
    for (int off = 16; off >= 1; off >>= 1) {
        if (c < off) {
            float4 o4 = sacc[c + off][q];
            float4 m = sacc[c][q];
            m.x += o4.x; m.y += o4.y; m.z += o4.z; m.w += o4.w;
            sacc[c][q] = m;
        }
        __syncthreads();
    }
    if (tid < 16) ((float4*)g_xsum)[b * (SS / 4) + sc * 16 + tid] = sacc[0][tid];

    // side job: wsum row k = bx for blocks 0..31
    if (bx < 32) {
        int k = bx, cc = tid >> 5, o = tid & 31;
        float s = 0.f;
        {
            int idx = (k * CH + cc) * OC + o;
            s += (1.f / (1.f + expf(-wla[idx]))) * cosf(wph[idx]);
            idx = (k * CH + cc + 16) * OC + o;
            s += (1.f / (1.f + expf(-wla[idx]))) * cosf(wph[idx]);
        }
        sws[cc][o] = s;
        __syncthreads();
        if (tid < 32) {
            float t = 0.f;
            #pragma unroll
            for (int j = 0; j < 16; j++) t += sws[j][tid];
            g_wsum[k * OC + tid] = t;
        }
    }

    // ---- last block computes x_mean -> poles ----
    __threadfence();
    if (tid == 0) lastFlag = (atomicAdd(&g_cnt, 1) == 255);
    __syncthreads();
    if (!lastFlag) return;
    {
        int cc = tid & 31, r = tid >> 5;    // 16 rows of 16 blocks
        float s = 0.f;
        #pragma unroll
        for (int j = 0; j < 16; j++) s += g_cpart[(r * 16 + j) * 32 + cc];
        sxm[cc][r] = s;
    }
    __syncthreads();
    if (tid < 32) {
        float s = 0.f;
        #pragma unroll
        for (int r = 0; r < 16; r++) s += sxm[tid][r];
        sxm[tid][16] = s * (1.f / (float)(SB * SS));
    }
    __syncthreads();
    if (tid < 32) {
        int k = tid;
        float off = 0.f;
        #pragma unroll 8
        for (int cc = 0; cc < CH; cc++) off += sxm[cc][16] * pole_w[cc * KM + k];
        off = tanhf(off + pole_b[k]);
        float vv = log_poles[k] + 0.1f * off;
        float sp = fmaxf(vv, 0.f) + log1pf(expf(-fabsf(vv)));   // softplus
        float p = fminf(fmaxf(sp, 0.1f), 100.f);
        g_poles[k] = p;
        g_a[k]  = expf(-p * DF);
        g_aG[k] = expf(-p * DF * 64.f);
        if (k == 0) {
            float mx = c_star[0];
            for (int i = 1; i < SB; i++) mx = fmaxf(mx, c_star[i]);
            g_D = mx * dt_star[0];          // CAUSAL_SAFETY = 1
            g_cnt = 0;                      // reset for next graph replay
        }
    }
}

// ------- Stage 1: decay scans -> g_P/g_Q in [b][k][t], grid = (batch, dir) -------
__global__ __launch_bounds__(1024) void k_scan() {
    __shared__ __align__(16) float xs[SS];
    __shared__ float lc[32 * 33];
    __shared__ float sh_a[KM], sh_aG[KM];
    int b = blockIdx.x;
    int fwd = (blockIdx.y == 0);
    int tid = threadIdx.x;

    if (tid < 512) ((float4*)xs)[tid] = ((const float4*)(g_xsum + b * SS))[tid];
    if (tid < 32) { sh_a[tid] = g_a[tid]; sh_aG[tid] = g_aG[tid]; }
    __syncthreads();

    int j = tid >> 5, k = tid & 31;         // warp = chunk of 64, lane = mode
    float a = sh_a[k];
    const float4* c4 = (const float4*)xs + j * 16;

    // pass 1: chunk-local carry
    float s = 0.f;
    if (fwd) {
        #pragma unroll
        for (int i = 0; i < 16; i++) {
            float4 v = c4[i];
            s = fmaf(a, s, v.x); s = fmaf(a, s, v.y);
            s = fmaf(a, s, v.z); s = fmaf(a, s, v.w);
        }
    } else {
        #pragma unroll
        for (int i = 15; i >= 0; i--) {
            float4 v = c4[i];
            s = fmaf(a, s, v.w); s = fmaf(a, s, v.z);
            s = fmaf(a, s, v.y); s = fmaf(a, s, v.x);
        }
    }
    lc[j * 33 + k] = s;
    __syncthreads();

    // Kogge-Stone over chunks: warp j owns mode w=j, lanes = chunk (dir-mapped)
    {
        int w = j;
        int q = fwd ? k : (31 - k);
        float v = lc[q * 33 + w];
        float Ap = sh_aG[w];                // a^64
        #pragma unroll
        for (int d = 1; d < 32; d <<= 1) {
            float up = __shfl_up_sync(0xffffffffu, v, d);
            if (k >= d) v = fmaf(Ap, up, v);
            Ap = Ap * Ap;
        }
        float inc = __shfl_up_sync(0xffffffffu, v, 1);   // exclusive
        if (k == 0) inc = 0.f;
        lc[q * 33 + w] = inc;
    }
    __syncthreads();

    // pass 2: seeded scan, STG.128 x16 into [b][k][t]
    float* Zk = (fwd ? g_P : g_Q) + ((size_t)b * KM + k) * SS + j * 64;
    s = lc[j * 33 + k];
    if (fwd) {
        #pragma unroll
        for (int i = 0; i < 16; i++) {
            float4 v = c4[i], r;
            s = fmaf(a, s, v.x); r.x = s;
            s = fmaf(a, s, v.y); r.y = s;
            s = fmaf(a, s, v.z); r.z = s;
            s = fmaf(a, s, v.w); r.w = s;
            ((float4*)Zk)[i] = r;
        }
    } else {
        #pragma unroll
        for (int i = 15; i >= 0; i--) {
            float4 v = c4[i], r;
            s = fmaf(a, s, v.w); r.w = s;
            s = fmaf(a, s, v.z); r.z = s;
            s = fmaf(a, s, v.y); r.y = s;
            s = fmaf(a, s, v.x); r.x = s;
            ((float4*)Zk)[i] = r;
        }
    }
}

// ------- Stage 2: windows + z tile + GEMV, grid = (64, 8) -------
__global__ __launch_bounds__(256) void k_out(float* __restrict__ out) {
    __shared__ int smL[32], smR[32];
    __shared__ float sha[KM], sphk[KM], sinv[KM], sflt[KM];
    __shared__ __align__(16) float ws[KM * OC];
    __shared__ float zt[32 * 33];      // [tl][k] padded
    __shared__ float st[32 * 33];      // [tl][o] padded
    int t0 = blockIdx.x * 32, b = blockIdx.y;
    int tid = threadIdx.x;
    int w = tid >> 5, lane = tid & 31;

    ((float4*)ws)[tid] = ((const float4*)g_wsum)[tid];
    if (tid < 32) {
        float p = g_poles[tid];
        float ph = p * DF;
        sha[tid]  = g_a[tid];
        sphk[tid] = ph;
        sinv[tid] = 1.f / expm1f(-ph);
        float kn = (float)tid * (1.0f / (float)(KM - 1));
        sflt[tid] = expf(-4.f * kn * kn);
    }
    if (tid >= 32 && tid < 64) {             // exact float32 window search per row
        float D = g_D;
        int tl = tid - 32;
        int t = t0 + tl;
        float ct = coordf(t);
        int guess = (int)(D * 2047.0f) + 2;
        int hi = SS - 1 - t;
        int j = min(hi, max(0, guess));
        while (j > 0 && fabsf(coordf(t + j) - ct) > D) j--;
        while (j < hi && fabsf(coordf(t + j + 1) - ct) <= D) j++;
        smR[tl] = j;
        hi = t;
        j = min(hi, max(0, guess));
        while (j > 0 && fabsf(coordf(t - j) - ct) > D) j--;
        while (j < hi && fabsf(coordf(t - j - 1) - ct) <= D) j++;
        smL[tl] = j;
    }
    __syncthreads();

    // phase A: warp w -> modes k = 4w..4w+3, lane = t-within-tile (coalesced gathers)
    {
        int t = t0 + lane;
        int mL = smL[lane], mR = smR[lane];
        int tm = t - mL - 1, tp = t + mR + 1;
        #pragma unroll
        for (int kk = 0; kk < 4; kk++) {
            int k = w * 4 + kk;
            const float* Pk = g_P + ((size_t)b * KM + k) * SS;
            const float* Qk = g_Q + ((size_t)b * KM + k) * SS;
            float ph = sphk[k], inv_em = sinv[k];
            float P  = Pk[t];
            float Pm = (tm >= 0) ? Pk[tm] : 0.f;
            float Qp = (t + 1 < SS) ? Qk[t + 1] : 0.f;
            float Qm = (tp < SS) ? Qk[tp] : 0.f;
            float cLe = expm1f(-ph * (float)(mL + 1));
            float cRe = expm1f(-ph * (float)(mR + 1));
            float norm = fmaxf(fmaf(cLe, inv_em, cRe * inv_em) - 1.f, 1e-8f);
            float L = fmaf(-(cLe + 1.f), Pm, P);
            float R = fmaf(-(cRe + 1.f), Qm, sha[k] * Qp);
            zt[lane * 33 + k] = (L + R) * (sflt[k] / norm);
        }
    }
    __syncthreads();

    // phase B: GEMV, warp w rows tl = 4w..4w+3, lane = o
    #pragma unroll
    for (int q = 0; q < 4; q++) {
        int tl = w * 4 + q;
        const float* zr = zt + tl * 33;
        float acc = 0.f;
        #pragma unroll
        for (int k = 0; k < 32; k++)
            acc = fmaf(zr[k], ws[k * OC + lane], acc);   // zr[k] lane-uniform broadcast
        st[tl * 33 + lane] = acc;
    }
    __syncthreads();

    // store: thread -> (o = tid/8, 4 consecutive t) as STG.128
    int o = tid >> 3, i0 = (tid & 7) * 4;
    float4 r;
    r.x = st[(i0 + 0) * 33 + o];
    r.y = st[(i0 + 1) * 33 + o];
    r.z = st[(i0 + 2) * 33 + o];
    r.w = st[(i0 + 3) * 33 + o];
    *(float4*)(out + ((size_t)(b * OC + o)) * SS + t0 + i0) = r;
}

extern "C" void kernel_launch(void* const* d_in, const int* in_sizes, int n_in,
                              void* d_out, int out_size) {
    // size-based input resolution
    int ix = -1, ic = -1, idt = -1, iwla = -1, iwph = -1, ilp = -1, ipw = -1, ipb = -1;
    for (int i = 0; i < n_in; i++) {
        int s = in_sizes[i];
        if (s == SB * CH * SS)      { if (ix  < 0) ix  = i; }
        else if (s == SB)           { if (ic  < 0) ic  = i; }
        else if (s == KM * CH * OC) { if (iwla < 0) iwla = i; else if (iwph < 0) iwph = i; }
        else if (s == CH * KM)      { if (ipw < 0) ipw = i; }
        else if (s == KM)           { if (ilp < 0) ilp = i; else if (ipb < 0) ipb = i; }
        else if (s == 1)            { if (idt < 0) idt = i; }
    }
    const float* x   = (const float*)d_in[ix];
    const float* cs  = (const float*)d_in[ic];
    const float* dt  = (const float*)d_in[idt];
    const float* wla = (const float*)d_in[iwla];
    const float* wph = (const float*)d_in[iwph];
    const float* lp  = (const float*)d_in[ilp];
    const float* pw  = (const float*)d_in[ipw];
    const float* pb  = (const float*)d_in[ipb];
    float* out = (float*)d_out;

    k_pre<<<256, 512>>>(x, wla, wph, cs, dt, lp, pw, pb);
    k_scan<<<dim3(SB, 2), 1024>>>();
    k_out<<<dim3(SS / 32, SB), 256>>>(out);
}

// round 6
// speedup vs baseline: 1.0565x; 1.0565x over previous
#include <cuda_runtime.h>
#include <math.h>

#define SB 8
#define CH 32
#define KM 32
#define OC 32
#define SS 2048
#define DF (1.0f/2047.0f)

// ---- scratch (device globals: allocation-free rule) ----
__device__ __align__(16) float g_xsum[SB*SS];            // [b][s]
__device__ float g_cpart[256*CH];                        // per-block per-channel partials
__device__ __align__(16) float g_P[(size_t)SB*KM*SS];    // [b][k][t] fwd decay scan
__device__ __align__(16) float g_Q[(size_t)SB*KM*SS];    // [b][k][t] bwd decay scan
__device__ __align__(16) float g_wsum[KM*OC];            // [k][o]
__device__ float g_a[KM], g_poles[KM];
__device__ float g_D;

// replicate reference float32 coords: linspace(0,1,2048)
__device__ __forceinline__ float coordf(int i) {
    return (i == SS - 1) ? 1.0f : ((float)i) * DF;
}

// ------- Stage 0: xsum + cpart (256 blocks, 1 LDG.128/thread); blocks 0..31 wsum -------
__global__ __launch_bounds__(512) void k_pre(
    const float* __restrict__ x, const float* __restrict__ wla,
    const float* __restrict__ wph)
{
    __shared__ __align__(16) float4 sacc[32][16];
    __shared__ float sws[16][32];
    int bx = blockIdx.x;
    int b = bx >> 5, sc = bx & 31;          // 32 s-chunks of 64 elements
    int tid = threadIdx.x;
    int c = tid >> 4, q = tid & 15;         // channel, quad-within-chunk
    int lane = tid & 31;

    float4 v = ((const float4*)x)[(size_t)(b * CH + c) * (SS / 4) + sc * 16 + q];
    sacc[c][q] = v;
    float cp = (v.x + v.y) + (v.z + v.w);
    cp += __shfl_xor_sync(0xffffffffu, cp, 1);
    cp += __shfl_xor_sync(0xffffffffu, cp, 2);
    cp += __shfl_xor_sync(0xffffffffu, cp, 4);
    cp += __shfl_xor_sync(0xffffffffu, cp, 8);
    if ((lane & 15) == 0) g_cpart[bx * 32 + c] = cp;
    __syncthreads();
    #pragma unroll
    for (int off = 16; off >= 1; off >>= 1) {
        if (c < off) {
            float4 o4 = sacc[c + off][q];
            float4 m = sacc[c][q];
            m.x += o4.x; m.y += o4.y; m.z += o4.z; m.w += o4.w;
            sacc[c][q] = m;
        }
        __syncthreads();
    }
    if (tid < 16) ((float4*)g_xsum)[b * (SS / 4) + sc * 16 + tid] = sacc[0][tid];

    // side job: wsum row k = bx for blocks 0..31
    if (bx < 32) {
        int k = bx, cc = tid >> 5, o = tid & 31;
        float s = 0.f;
        {
            int idx = (k * CH + cc) * OC + o;
            s += (1.f / (1.f + expf(-wla[idx]))) * cosf(wph[idx]);
            idx = (k * CH + cc + 16) * OC + o;
            s += (1.f / (1.f + expf(-wla[idx]))) * cosf(wph[idx]);
        }
        sws[cc][o] = s;
        __syncthreads();
        if (tid < 32) {
            float t = 0.f;
            #pragma unroll
            for (int j = 0; j < 16; j++) t += sws[j][tid];
            g_wsum[k * OC + tid] = t;
        }
    }
}

// ------- Stage 1: decay scans (poles inline) -> g_P/g_Q [b][k][t], grid = (batch, dir) -------
__global__ __launch_bounds__(1024) void k_scan(
    const float* __restrict__ c_star, const float* __restrict__ dt_star,
    const float* __restrict__ log_poles, const float* __restrict__ pole_w,
    const float* __restrict__ pole_b)
{
    __shared__ __align__(16) float xs[SS];
    __shared__ float lc[32 * 33];
    __shared__ float sxm[32][34];           // [c][r partials + mean]
    __shared__ float sh_a[KM], sh_aG[KM];
    int b = blockIdx.x;
    int fwd = (blockIdx.y == 0);
    int tid = threadIdx.x;

    if (tid < 512) ((float4*)xs)[tid] = ((const float4*)(g_xsum + b * SS))[tid];

    {                                       // cpart reduce: c = tid&31, 32 rows of 8
        int c = tid & 31, r = tid >> 5;
        float s = 0.f;
        #pragma unroll
        for (int j = 0; j < 8; j++) s += g_cpart[(r * 8 + j) * 32 + c];
        sxm[c][r] = s;
    }
    __syncthreads();
    if (tid < 32) {
        float s = 0.f;
        #pragma unroll
        for (int r = 0; r < 32; r++) s += sxm[tid][r];
        sxm[tid][33] = s * (1.f / (float)(SB * SS));
    }
    __syncthreads();
    if (tid < 32) {
        int k = tid;
        float off = 0.f;
        #pragma unroll 8
        for (int cc = 0; cc < CH; cc++) off += sxm[cc][33] * pole_w[cc * KM + k];
        off = tanhf(off + pole_b[k]);
        float vv = log_poles[k] + 0.1f * off;
        float sp = fmaxf(vv, 0.f) + log1pf(expf(-fabsf(vv)));   // softplus
        float p = fminf(fmaxf(sp, 0.1f), 100.f);
        sh_a[k]  = expf(-p * DF);
        sh_aG[k] = expf(-p * DF * 64.f);
        if (b == 0 && fwd) {
            g_poles[k] = p;
            g_a[k] = sh_a[k];
            if (k == 0) {
                float mx = c_star[0];
                for (int i = 1; i < SB; i++) mx = fmaxf(mx, c_star[i]);
                g_D = mx * dt_star[0];      // CAUSAL_SAFETY = 1
            }
        }
    }
    __syncthreads();

    int j = tid >> 5, k = tid & 31;         // warp = chunk of 64, lane = mode
    float a = sh_a[k];
    const float4* c4 = (const float4*)xs + j * 16;

    // pass 1: chunk-local carry
    float s = 0.f;
    if (fwd) {
        #pragma unroll
        for (int i = 0; i < 16; i++) {
            float4 v = c4[i];
            s = fmaf(a, s, v.x); s = fmaf(a, s, v.y);
            s = fmaf(a, s, v.z); s = fmaf(a, s, v.w);
        }
    } else {
        #pragma unroll
        for (int i = 15; i >= 0; i--) {
            float4 v = c4[i];
            s = fmaf(a, s, v.w); s = fmaf(a, s, v.z);
            s = fmaf(a, s, v.y); s = fmaf(a, s, v.x);
        }
    }
    lc[j * 33 + k] = s;
    __syncthreads();

    // Kogge-Stone over chunks: warp j owns mode w=j, lanes = chunk (dir-mapped)
    {
        int w = j;
        int q = fwd ? k : (31 - k);
        float v = lc[q * 33 + w];
        float Ap = sh_aG[w];                // a^64
        #pragma unroll
        for (int d = 1; d < 32; d <<= 1) {
            float up = __shfl_up_sync(0xffffffffu, v, d);
            if (k >= d) v = fmaf(Ap, up, v);
            Ap = Ap * Ap;
        }
        float inc = __shfl_up_sync(0xffffffffu, v, 1);   // exclusive
        if (k == 0) inc = 0.f;
        lc[q * 33 + w] = inc;
    }
    __syncthreads();

    // pass 2: seeded scan, 16x STG.128 into [b][k][t]
    float* Zk = (fwd ? g_P : g_Q) + ((size_t)b * KM + k) * SS + j * 64;
    s = lc[j * 33 + k];
    if (fwd) {
        #pragma unroll
        for (int i = 0; i < 16; i++) {
            float4 v = c4[i], r;
            s = fmaf(a, s, v.x); r.x = s;
            s = fmaf(a, s, v.y); r.y = s;
            s = fmaf(a, s, v.z); r.z = s;
            s = fmaf(a, s, v.w); r.w = s;
            ((float4*)Zk)[i] = r;
        }
    } else {
        #pragma unroll
        for (int i = 15; i >= 0; i--) {
            float4 v = c4[i], r;
            s = fmaf(a, s, v.w); r.w = s;
            s = fmaf(a, s, v.z); r.z = s;
            s = fmaf(a, s, v.y); r.y = s;
            s = fmaf(a, s, v.x); r.x = s;
            ((float4*)Zk)[i] = r;
        }
    }
}

// ------- Stage 2: windows + z tile + GEMV, grid = (64, 8) -------
__global__ __launch_bounds__(256) void k_out(float* __restrict__ out) {
    __shared__ int smL[32], smR[32];
    __shared__ float sha[KM], sphk[KM], sinv[KM], sflt[KM];
    __shared__ __align__(16) float ws[KM * OC];
    __shared__ float zt[32 * 33];      // [tl][k] padded
    __shared__ float st[32 * 33];      // [tl][o] padded
    int t0 = blockIdx.x * 32, b = blockIdx.y;
    int tid = threadIdx.x;
    int w = tid >> 5, lane = tid & 31;

    ((float4*)ws)[tid] = ((const float4*)g_wsum)[tid];
    if (tid < 32) {
        float p = g_poles[tid];
        float ph = p * DF;
        sha[tid]  = g_a[tid];
        sphk[tid] = ph;
        sinv[tid] = 1.f / expm1f(-ph);
        float kn = (float)tid * (1.0f / (float)(KM - 1));
        sflt[tid] = expf(-4.f * kn * kn);
    }
    if (tid >= 32 && tid < 64) {             // exact float32 window search per row
        float D = g_D;
        int tl = tid - 32;
        int t = t0 + tl;
        float ct = coordf(t);
        int guess = (int)(D * 2047.0f) + 2;
        int hi = SS - 1 - t;
        int j = min(hi, max(0, guess));
        while (j > 0 && fabsf(coordf(t + j) - ct) > D) j--;
        while (j < hi && fabsf(coordf(t + j + 1) - ct) <= D) j++;
        smR[tl] = j;
        hi = t;
        j = min(hi, max(0, guess));
        while (j > 0 && fabsf(coordf(t - j) - ct) > D) j--;
        while (j < hi && fabsf(coordf(t - j - 1) - ct) <= D) j++;
        smL[tl] = j;
    }
    __syncthreads();

    // phase A: warp w -> modes k = 4w..4w+3, lane = t-within-tile (coalesced gathers)
    {
        int t = t0 + lane;
        int mL = smL[lane], mR = smR[lane];
        int tm = t - mL - 1, tp = t + mR + 1;
        #pragma unroll
        for (int kk = 0; kk < 4; kk++) {
            int k = w * 4 + kk;
            const float* Pk = g_P + ((size_t)b * KM + k) * SS;
            const float* Qk = g_Q + ((size_t)b * KM + k) * SS;
            float ph = sphk[k], inv_em = sinv[k];
            float P  = Pk[t];
            float Pm = (tm >= 0) ? Pk[tm] : 0.f;
            float Qp = (t + 1 < SS) ? Qk[t + 1] : 0.f;
            float Qm = (tp < SS) ? Qk[tp] : 0.f;
            float cLe = expm1f(-ph * (float)(mL + 1));
            float cRe = expm1f(-ph * (float)(mR + 1));
            float norm = fmaxf(fmaf(cLe, inv_em, cRe * inv_em) - 1.f, 1e-8f);
            float L = fmaf(-(cLe + 1.f), Pm, P);
            float R = fmaf(-(cRe + 1.f), Qm, sha[k] * Qp);
            zt[lane * 33 + k] = (L + R) * (sflt[k] / norm);
        }
    }
    __syncthreads();

    // phase B: GEMV, warp w rows tl = 4w..4w+3, lane = o
    #pragma unroll
    for (int q = 0; q < 4; q++) {
        int tl = w * 4 + q;
        const float* zr = zt + tl * 33;
        float acc = 0.f;
        #pragma unroll
        for (int k = 0; k < 32; k++)
            acc = fmaf(zr[k], ws[k * OC + lane], acc);   // zr[k] lane-uniform broadcast
        st[tl * 33 + lane] = acc;
    }
    __syncthreads();

    // store: thread -> (o = tid/8, 4 consecutive t) as STG.128
    int o = tid >> 3, i0 = (tid & 7) * 4;
    float4 r;
    r.x = st[(i0 + 0) * 33 + o];
    r.y = st[(i0 + 1) * 33 + o];
    r.z = st[(i0 + 2) * 33 + o];
    r.w = st[(i0 + 3) * 33 + o];
    *(float4*)(out + ((size_t)(b * OC + o)) * SS + t0 + i0) = r;
}

extern "C" void kernel_launch(void* const* d_in, const int* in_sizes, int n_in,
                              void* d_out, int out_size) {
    // size-based input resolution
    int ix = -1, ic = -1, idt = -1, iwla = -1, iwph = -1, ilp = -1, ipw = -1, ipb = -1;
    for (int i = 0; i < n_in; i++) {
        int s = in_sizes[i];
        if (s == SB * CH * SS)      { if (ix  < 0) ix  = i; }
        else if (s == SB)           { if (ic  < 0) ic  = i; }
        else if (s == KM * CH * OC) { if (iwla < 0) iwla = i; else if (iwph < 0) iwph = i; }
        else if (s == CH * KM)      { if (ipw < 0) ipw = i; }
        else if (s == KM)           { if (ilp < 0) ilp = i; else if (ipb < 0) ipb = i; }
        else if (s == 1)            { if (idt < 0) idt = i; }
    }
    const float* x   = (const float*)d_in[ix];
    const float* cs  = (const float*)d_in[ic];
    const float* dt  = (const float*)d_in[idt];
    const float* wla = (const float*)d_in[iwla];
    const float* wph = (const float*)d_in[iwph];
    const float* lp  = (const float*)d_in[ilp];
    const float* pw  = (const float*)d_in[ipw];
    const float* pb  = (const float*)d_in[ipb];
    float* out = (float*)d_out;

    k_pre<<<256, 512>>>(x, wla, wph);
    k_scan<<<dim3(SB, 2), 1024>>>(cs, dt, lp, pw, pb);
    k_out<<<dim3(SS / 32, SB), 256>>>(out);
}

// round 7
// speedup vs baseline: 1.2738x; 1.2057x over previous
#include <cuda_runtime.h>
#include <math.h>

#define SB 8
#define CH 32
#define KM 32
#define OC 32
#define SS 2048
#define DF (1.0f/2047.0f)

// ---- scratch (device globals: allocation-free rule) ----
__device__ __align__(16) float g_xsum[SB*SS];            // [b][s]
__device__ float g_cpart[256*CH];                        // per-block per-channel partials
__device__ __align__(16) float g_P[(size_t)SB*SS*KM];    // [b][t][k] fwd decay scan
__device__ __align__(16) float g_Q[(size_t)SB*SS*KM];    // [b][t][k] bwd decay scan
__device__ __align__(16) float g_wsum[KM*OC];            // [k][o]
__device__ float g_a[KM], g_poles[KM];
__device__ float g_D;

// replicate reference float32 coords: linspace(0,1,2048)
__device__ __forceinline__ float coordf(int i) {
    return (i == SS - 1) ? 1.0f : ((float)i) * DF;
}

// ------- Stage 0: xsum + cpart (256 blocks, 1 LDG.128/thread); blocks 0..31 wsum -------
__global__ __launch_bounds__(512) void k_pre(
    const float* __restrict__ x, const float* __restrict__ wla,
    const float* __restrict__ wph)
{
    __shared__ __align__(16) float4 sacc[32][16];
    __shared__ float sws[16][32];
    int bx = blockIdx.x;
    int b = bx >> 5, sc = bx & 31;          // 32 s-chunks of 64 elements
    int tid = threadIdx.x;
    int c = tid >> 4, q = tid & 15;         // channel, quad-within-chunk
    int lane = tid & 31;

    float4 v = ((const float4*)x)[(size_t)(b * CH + c) * (SS / 4) + sc * 16 + q];
    sacc[c][q] = v;
    float cp = (v.x + v.y) + (v.z + v.w);
    cp += __shfl_xor_sync(0xffffffffu, cp, 1);
    cp += __shfl_xor_sync(0xffffffffu, cp, 2);
    cp += __shfl_xor_sync(0xffffffffu, cp, 4);
    cp += __shfl_xor_sync(0xffffffffu, cp, 8);
    if ((lane & 15) == 0) g_cpart[bx * 32 + c] = cp;
    __syncthreads();
    #pragma unroll
    for (int off = 16; off >= 1; off >>= 1) {
        if (c < off) {
            float4 o4 = sacc[c + off][q];
            float4 m = sacc[c][q];
            m.x += o4.x; m.y += o4.y; m.z += o4.z; m.w += o4.w;
            sacc[c][q] = m;
        }
        __syncthreads();
    }
    if (tid < 16) ((float4*)g_xsum)[b * (SS / 4) + sc * 16 + tid] = sacc[0][tid];

    // side job: wsum row k = bx for blocks 0..31
    if (bx < 32) {
        int k = bx, cc = tid >> 5, o = tid & 31;
        float s = 0.f;
        {
            int idx = (k * CH + cc) * OC + o;
            s += (1.f / (1.f + expf(-wla[idx]))) * cosf(wph[idx]);
            idx = (k * CH + cc + 16) * OC + o;
            s += (1.f / (1.f + expf(-wla[idx]))) * cosf(wph[idx]);
        }
        sws[cc][o] = s;
        __syncthreads();
        if (tid < 32) {
            float t = 0.f;
            #pragma unroll
            for (int j = 0; j < 16; j++) t += sws[j][tid];
            g_wsum[k * OC + tid] = t;
        }
    }
}

// ------- Stage 1: decay scans (poles inline) -> g_P/g_Q [b][t][k] -------
// Block = 256 threads: thread = (chunk j = tid>>3, kgroup m = tid&7) holds 4 modes.
__global__ __launch_bounds__(256) void k_scan(
    const float* __restrict__ c_star, const float* __restrict__ dt_star,
    const float* __restrict__ log_poles, const float* __restrict__ pole_w,
    const float* __restrict__ pole_b)
{
    __shared__ __align__(16) float xs[SS];
    __shared__ float lc[32 * 33];           // [chunk][k] carries
    __shared__ float sxm[32][9];
    __shared__ float sh_a[KM], sh_aG[KM];
    int b = blockIdx.x;
    int fwd = (blockIdx.y == 0);
    int tid = threadIdx.x;

    {
        const float4* src = (const float4*)(g_xsum + b * SS);
        ((float4*)xs)[tid]       = src[tid];
        ((float4*)xs)[tid + 256] = src[tid + 256];
    }
    {                                       // cpart reduce: c = tid&31, 8 rows of 32 blocks
        int c = tid & 31, r = tid >> 5;
        float s = 0.f;
        #pragma unroll
        for (int j = 0; j < 32; j++) s += g_cpart[(r * 32 + j) * 32 + c];
        sxm[c][r] = s;
    }
    __syncthreads();
    if (tid < 32) {
        float s = 0.f;
        #pragma unroll
        for (int r = 0; r < 8; r++) s += sxm[tid][r];
        sxm[tid][8] = s * (1.f / (float)(SB * SS));
    }
    __syncthreads();
    if (tid < 32) {
        int k = tid;
        float off = 0.f;
        #pragma unroll 8
        for (int cc = 0; cc < CH; cc++) off += sxm[cc][8] * pole_w[cc * KM + k];
        off = tanhf(off + pole_b[k]);
        float vv = log_poles[k] + 0.1f * off;
        float sp = fmaxf(vv, 0.f) + log1pf(expf(-fabsf(vv)));   // softplus
        float p = fminf(fmaxf(sp, 0.1f), 100.f);
        sh_a[k]  = expf(-p * DF);
        sh_aG[k] = expf(-p * DF * 64.f);
        if (b == 0 && fwd) {
            g_poles[k] = p;
            g_a[k] = sh_a[k];
            if (k == 0) {
                float mx = c_star[0];
                for (int i = 1; i < SB; i++) mx = fmaxf(mx, c_star[i]);
                g_D = mx * dt_star[0];      // CAUSAL_SAFETY = 1
            }
        }
    }
    __syncthreads();

    int j = tid >> 3, m = tid & 7;          // chunk of 64 t, mode-group (4 modes)
    float a0 = sh_a[4*m+0], a1 = sh_a[4*m+1], a2 = sh_a[4*m+2], a3 = sh_a[4*m+3];
    const float4* c4 = (const float4*)xs + j * 16;

    // pass 1: chunk-local carries for 4 modes (4-way ILP)
    float s0 = 0.f, s1 = 0.f, s2 = 0.f, s3 = 0.f;
    if (fwd) {
        #pragma unroll
        for (int i = 0; i < 16; i++) {
            float4 v = c4[i];
            s0=fmaf(a0,s0,v.x); s1=fmaf(a1,s1,v.x); s2=fmaf(a2,s2,v.x); s3=fmaf(a3,s3,v.x);
            s0=fmaf(a0,s0,v.y); s1=fmaf(a1,s1,v.y); s2=fmaf(a2,s2,v.y); s3=fmaf(a3,s3,v.y);
            s0=fmaf(a0,s0,v.z); s1=fmaf(a1,s1,v.z); s2=fmaf(a2,s2,v.z); s3=fmaf(a3,s3,v.z);
            s0=fmaf(a0,s0,v.w); s1=fmaf(a1,s1,v.w); s2=fmaf(a2,s2,v.w); s3=fmaf(a3,s3,v.w);
        }
    } else {
        #pragma unroll
        for (int i = 15; i >= 0; i--) {
            float4 v = c4[i];
            s0=fmaf(a0,s0,v.w); s1=fmaf(a1,s1,v.w); s2=fmaf(a2,s2,v.w); s3=fmaf(a3,s3,v.w);
            s0=fmaf(a0,s0,v.z); s1=fmaf(a1,s1,v.z); s2=fmaf(a2,s2,v.z); s3=fmaf(a3,s3,v.z);
            s0=fmaf(a0,s0,v.y); s1=fmaf(a1,s1,v.y); s2=fmaf(a2,s2,v.y); s3=fmaf(a3,s3,v.y);
            s0=fmaf(a0,s0,v.x); s1=fmaf(a1,s1,v.x); s2=fmaf(a2,s2,v.x); s3=fmaf(a3,s3,v.x);
        }
    }
    lc[j * 33 + 4*m+0] = s0; lc[j * 33 + 4*m+1] = s1;
    lc[j * 33 + 4*m+2] = s2; lc[j * 33 + 4*m+3] = s3;
    __syncthreads();

    // Kogge-Stone over chunks: warp w handles modes 4w..4w+3, lanes = chunk (dir-mapped)
    {
        int w = tid >> 5, lane = tid & 31;
        int q = fwd ? lane : (31 - lane);
        #pragma unroll
        for (int i = 0; i < 4; i++) {
            int k = 4 * w + i;
            float v = lc[q * 33 + k];
            float Ap = sh_aG[k];            // a^64
            #pragma unroll
            for (int d = 1; d < 32; d <<= 1) {
                float up = __shfl_up_sync(0xffffffffu, v, d);
                if (lane >= d) v = fmaf(Ap, up, v);
                Ap = Ap * Ap;
            }
            float inc = __shfl_up_sync(0xffffffffu, v, 1);   // exclusive
            if (lane == 0) inc = 0.f;
            lc[q * 33 + k] = inc;
        }
    }
    __syncthreads();

    // pass 2: seeded, one coalesced STG.128 per t covering k = 4m..4m+3
    float* Zt = (fwd ? g_P : g_Q) + (size_t)b * SS * KM;
    s0 = lc[j * 33 + 4*m+0]; s1 = lc[j * 33 + 4*m+1];
    s2 = lc[j * 33 + 4*m+2]; s3 = lc[j * 33 + 4*m+3];
    int t0 = j * 64;
    if (fwd) {
        #pragma unroll
        for (int i = 0; i < 16; i++) {
            float4 v = c4[i];
            s0=fmaf(a0,s0,v.x); s1=fmaf(a1,s1,v.x); s2=fmaf(a2,s2,v.x); s3=fmaf(a3,s3,v.x);
            *(float4*)(Zt + (size_t)(t0 + 4*i + 0) * KM + 4*m) = make_float4(s0,s1,s2,s3);
            s0=fmaf(a0,s0,v.y); s1=fmaf(a1,s1,v.y); s2=fmaf(a2,s2,v.y); s3=fmaf(a3,s3,v.y);
            *(float4*)(Zt + (size_t)(t0 + 4*i + 1) * KM + 4*m) = make_float4(s0,s1,s2,s3);
            s0=fmaf(a0,s0,v.z); s1=fmaf(a1,s1,v.z); s2=fmaf(a2,s2,v.z); s3=fmaf(a3,s3,v.z);
            *(float4*)(Zt + (size_t)(t0 + 4*i + 2) * KM + 4*m) = make_float4(s0,s1,s2,s3);
            s0=fmaf(a0,s0,v.w); s1=fmaf(a1,s1,v.w); s2=fmaf(a2,s2,v.w); s3=fmaf(a3,s3,v.w);
            *(float4*)(Zt + (size_t)(t0 + 4*i + 3) * KM + 4*m) = make_float4(s0,s1,s2,s3);
        }
    } else {
        #pragma unroll
        for (int i = 15; i >= 0; i--) {
            float4 v = c4[i];
            s0=fmaf(a0,s0,v.w); s1=fmaf(a1,s1,v.w); s2=fmaf(a2,s2,v.w); s3=fmaf(a3,s3,v.w);
            *(float4*)(Zt + (size_t)(t0 + 4*i + 3) * KM + 4*m) = make_float4(s0,s1,s2,s3);
            s0=fmaf(a0,s0,v.z); s1=fmaf(a1,s1,v.z); s2=fmaf(a2,s2,v.z); s3=fmaf(a3,s3,v.z);
            *(float4*)(Zt + (size_t)(t0 + 4*i + 2) * KM + 4*m) = make_float4(s0,s1,s2,s3);
            s0=fmaf(a0,s0,v.y); s1=fmaf(a1,s1,v.y); s2=fmaf(a2,s2,v.y); s3=fmaf(a3,s3,v.y);
            *(float4*)(Zt + (size_t)(t0 + 4*i + 1) * KM + 4*m) = make_float4(s0,s1,s2,s3);
            s0=fmaf(a0,s0,v.x); s1=fmaf(a1,s1,v.x); s2=fmaf(a2,s2,v.x); s3=fmaf(a3,s3,v.x);
            *(float4*)(Zt + (size_t)(t0 + 4*i + 0) * KM + 4*m) = make_float4(s0,s1,s2,s3);
        }
    }
}

// ------- Stage 2: windows + z tile + GEMV, grid = (64, 8)  [round-4 version] -------
__global__ __launch_bounds__(256) void k_out(float* __restrict__ out) {
    __shared__ int smL[32], smR[32];
    __shared__ float shp[KM], sha[KM];
    __shared__ __align__(16) float ws[KM * OC];
    __shared__ __align__(16) float zt[32 * 32];
    __shared__ float st[32 * 33];
    int t0 = blockIdx.x * 32, b = blockIdx.y;
    int tid = threadIdx.x;
    int w = tid >> 5, lane = tid & 31;

    ((float4*)ws)[tid] = ((const float4*)g_wsum)[tid];
    if (tid < 32) { shp[tid] = g_poles[tid]; sha[tid] = g_a[tid]; }

    if (tid >= 32 && tid < 64) {             // exact float32 window search per row
        float D = g_D;
        int tl = tid - 32;
        int t = t0 + tl;
        float ct = coordf(t);
        int guess = (int)(D * 2047.0f) + 2;
        int hi = SS - 1 - t;
        int j = min(hi, max(0, guess));
        while (j > 0 && fabsf(coordf(t + j) - ct) > D) j--;
        while (j < hi && fabsf(coordf(t + j + 1) - ct) <= D) j++;
        smR[tl] = j;
        hi = t;
        j = min(hi, max(0, guess));
        while (j > 0 && fabsf(coordf(t - j) - ct) > D) j--;
        while (j < hi && fabsf(coordf(t - j - 1) - ct) <= D) j++;
        smL[tl] = j;
    }
    __syncthreads();

    const float* Pb = g_P + (size_t)b * SS * KM;
    const float* Qb = g_Q + (size_t)b * SS * KM;
    float a = sha[lane];
    float ph = shp[lane] * DF;
    float em = expm1f(-ph);
    float kn = (float)lane * (1.0f / (float)(KM - 1));
    float filt = expf(-4.f * kn * kn);

    // phase A: rows tl = w + 8q, lane = k; coefs in registers
    #pragma unroll
    for (int q = 0; q < 4; q++) {
        int tl = w + 8 * q;
        int t = t0 + tl;
        int mL = smL[tl], mR = smR[tl];
        float P  = Pb[(size_t)t * KM + lane];
        int tm = t - mL - 1;
        float Pm = (tm >= 0) ? Pb[(size_t)tm * KM + lane] : 0.f;
        float Qp = (t + 1 < SS) ? Qb[(size_t)(t + 1) * KM + lane] : 0.f;
        int tp = t + mR + 1;
        float Qm = (tp < SS) ? Qb[(size_t)tp * KM + lane] : 0.f;
        float cLe = expm1f(-ph * (float)(mL + 1));
        float cRe = expm1f(-ph * (float)(mR + 1));
        float norm = fmaxf(cLe / em + cRe / em - 1.f, 1e-8f);
        float L = fmaf(-(cLe + 1.f), Pm, P);
        float R = fmaf(-(cRe + 1.f), Qm, a * Qp);
        zt[tl * 32 + lane] = (L + R) * (filt / norm);
    }
    __syncthreads();

    // phase B: GEMV, warp w rows tl = 4w..4w+3, lane = o
    #pragma unroll
    for (int q = 0; q < 4; q++) {
        int tl = w * 4 + q;
        const float4* zr = (const float4*)(zt + tl * 32);
        float acc = 0.f;
        #pragma unroll
        for (int p = 0; p < 8; p++) {
            float4 zv = zr[p];               // lane-uniform broadcast
            acc = fmaf(zv.x, ws[(p * 4 + 0) * OC + lane], acc);
            acc = fmaf(zv.y, ws[(p * 4 + 1) * OC + lane], acc);
            acc = fmaf(zv.z, ws[(p * 4 + 2) * OC + lane], acc);
            acc = fmaf(zv.w, ws[(p * 4 + 3) * OC + lane], acc);
        }
        st[tl * 33 + lane] = acc;
    }
    __syncthreads();

    // store: thread -> (o = tid/8, 4 consecutive t) as STG.128
    int o = tid >> 3, i0 = (tid & 7) * 4;
    float4 r;
    r.x = st[(i0 + 0) * 33 + o];
    r.y = st[(i0 + 1) * 33 + o];
    r.z = st[(i0 + 2) * 33 + o];
    r.w = st[(i0 + 3) * 33 + o];
    *(float4*)(out + ((size_t)(b * OC + o)) * SS + t0 + i0) = r;
}

extern "C" void kernel_launch(void* const* d_in, const int* in_sizes, int n_in,
                              void* d_out, int out_size) {
    // size-based input resolution
    int ix = -1, ic = -1, idt = -1, iwla = -1, iwph = -1, ilp = -1, ipw = -1, ipb = -1;
    for (int i = 0; i < n_in; i++) {
        int s = in_sizes[i];
        if (s == SB * CH * SS)      { if (ix  < 0) ix  = i; }
        else if (s == SB)           { if (ic  < 0) ic  = i; }
        else if (s == KM * CH * OC) { if (iwla < 0) iwla = i; else if (iwph < 0) iwph = i; }
        else if (s == CH * KM)      { if (ipw < 0) ipw = i; }
        else if (s == KM)           { if (ilp < 0) ilp = i; else if (ipb < 0) ipb = i; }
        else if (s == 1)            { if (idt < 0) idt = i; }
    }
    const float* x   = (const float*)d_in[ix];
    const float* cs  = (const float*)d_in[ic];
    const float* dt  = (const float*)d_in[idt];
    const float* wla = (const float*)d_in[iwla];
    const float* wph = (const float*)d_in[iwph];
    const float* lp  = (const float*)d_in[ilp];
    const float* pw  = (const float*)d_in[ipw];
    const float* pb  = (const float*)d_in[ipb];
    float* out = (float*)d_out;

    k_pre<<<256, 512>>>(x, wla, wph);
    k_scan<<<dim3(SB, 2), 256>>>(cs, dt, lp, pw, pb);
    k_out<<<dim3(SS / 32, SB), 256>>>(out);
}